// round 7
// baseline (speedup 1.0000x reference)
#include <cuda_runtime.h>
#include <math.h>

#define BATCH 64
#define SEQ   512
#define EMBED 256
#define HID   512
#define GD    768     // HID + EMBED
#define NCLS  4

#define NBLK  128     // 2 batch halves x 64 column groups
#define NTHR  512     // 16 warps = 4 per SMSP
#define BG    32      // batch rows per CTA
#define ND    32      // dot-columns per CTA = 4 gates * 8 hidden units
#define K4T   192     // GD / 4 (float4 count per row)
#define HALF_CTAS 64

// SMEM: w[32][768] + inp[32][768] (XOR-swizzled) + 8 partial sets + bias
#define SM_W       0
#define SM_INP     (32*768)
#define SM_PART    (SM_INP + 32*768)
#define SET_STRIDE 1056                 // 32 cols' x 33 (row-padded)
#define SM_BIAS    (SM_PART + 8*SET_STRIDE)
#define SMEM_FLOATS (SM_BIAS + 32)
#define SMEM_BYTES  (SMEM_FLOATS * 4)   // 230,528 B

__device__ float g_h[2][BATCH*HID];
__device__ float g_maxh[BATCH*HID];
__device__ unsigned long long g_cnt;          // full-grid ticket counter
__device__ unsigned long long g_half[64];     // per-half arrival counters (slots 0, 32)

__device__ __forceinline__ float sigf(float x)     { return 1.0f / (1.0f + __expf(-x)); }
__device__ __forceinline__ float tanhfast(float x) { return 2.0f / (1.0f + __expf(-2.0f*x)) - 1.0f; }

__device__ __forceinline__ void fma2(unsigned long long &d,
                                     unsigned long long a, unsigned long long b) {
    asm("fma.rn.f32x2 %0, %1, %2, %0;" : "+l"(d) : "l"(a), "l"(b));
}
__device__ __forceinline__ float sum2(unsigned long long v) {
    float lo, hi;
    asm("mov.b64 {%0,%1}, %2;" : "=f"(lo), "=f"(hi) : "l"(v));
    return lo + hi;
}

// cp.async 16B, L2-only (.cg): required for h (cross-SM coherence), fine for emb
__device__ __forceinline__ void cp16_cg(unsigned int saddr, const void* g) {
    asm volatile("cp.async.cg.shared.global [%0], [%1], 16;" :: "r"(saddr), "l"(g));
}
#define CP_COMMIT()  asm volatile("cp.async.commit_group;" ::: "memory")
#define CP_WAITALL() asm volatile("cp.async.wait_all;"     ::: "memory")

// Full-grid ticket barrier (fence-free; init and finish only).
__device__ __forceinline__ void ticket_barrier() {
    __syncthreads();
    if (threadIdx.x == 0) {
        unsigned long long ticket;
        asm volatile("atom.release.gpu.add.u64 %0, [%1], %2;"
                     : "=l"(ticket) : "l"(&g_cnt), "l"(1ULL) : "memory");
        unsigned long long target = (ticket / NBLK + 1ULL) * (unsigned long long)NBLK;
        unsigned long long cur;
        do {
            asm volatile("ld.acquire.gpu.u64 %0, [%1];"
                         : "=l"(cur) : "l"(&g_cnt) : "memory");
        } while (cur < target);
    }
    __syncthreads();
}

// Per-half barrier: no-return release reduction + acquire poll vs per-replay base.
__device__ __forceinline__ void half_barrier(unsigned long long* ctr,
                                             unsigned long long target) {
    __syncthreads();
    if (threadIdx.x == 0) {
        asm volatile("red.release.gpu.add.u64 [%0], %1;"
                     :: "l"(ctr), "l"(1ULL) : "memory");
        unsigned long long cur;
        do {
            asm volatile("ld.acquire.gpu.u64 %0, [%1];"
                         : "=l"(cur) : "l"(ctr) : "memory");
        } while (cur < target);
    }
    __syncthreads();
}

__device__ __forceinline__ void loadx2(ulonglong2 xv[2], const float* xr0, int k4, int rg) {
    int ox = ((k4 ^ rg) << 2);
    xv[0] = *(const ulonglong2*)(xr0 + ox);
    xv[1] = *(const ulonglong2*)(xr0 + GD + ox);
}

__device__ __forceinline__ void gemm_step(unsigned long long acc[2][8],
                                          const ulonglong2 xv[2],
                                          const float* wc0, int o0, int o1) {
    #pragma unroll
    for (int c = 0; c < 8; c++) {
        ulonglong2 wv = *(const ulonglong2*)(wc0 + c*GD + (c < 4 ? o0 : o1));
        #pragma unroll
        for (int r = 0; r < 2; r++) {
            fma2(acc[r][c], xv[r].x, wv.x);
            fma2(acc[r][c], xv[r].y, wv.y);
        }
    }
}

extern "C" __global__ void __launch_bounds__(NTHR, 1)
lstm_persistent(const int*   __restrict__ ids,
                const float* __restrict__ emb,
                const float* __restrict__ Wf, const float* __restrict__ bf,
                const float* __restrict__ Wi, const float* __restrict__ bi,
                const float* __restrict__ Wo, const float* __restrict__ bo,
                const float* __restrict__ Wc, const float* __restrict__ bc,
                const float* __restrict__ fcw, const float* __restrict__ fcb,
                float* __restrict__ out)
{
    extern __shared__ float sm[];
    float* w_s    = sm + SM_W;
    float* inp_s  = sm + SM_INP;
    float* part_s = sm + SM_PART;
    float* bias_s = sm + SM_BIAS;

    const int tid  = threadIdx.x;
    const int cta  = blockIdx.x;
    const int half = cta & 1;
    const int b0   = half * BG;             // batch half
    const int j0   = (cta >> 1) * 8;        // hidden-unit group (8 units)
    const int wid  = tid >> 5;              // 0..15
    const int lane = tid & 31;

    unsigned long long* hctr = &g_half[half * 32];

    const float* Wg[4]  = {Wf, Wi, Wo, Wc};
    const float* bgp[4] = {bf, bi, bo, bc};

    // ---- one-time: weight slice into swizzled SMEM (col key (d>>2)&7) ----
    for (int idx = tid; idx < ND*K4T; idx += NTHR) {
        int d  = idx / K4T;
        int k4 = idx - d*K4T;
        int g  = d >> 3, jj = d & 7;
        float4 v = ((const float4*)(Wg[g] + (size_t)(j0 + jj) * GD))[k4];
        *(float4*)(w_s + d*GD + ((k4 ^ ((d >> 2) & 7)) << 2)) = v;
    }
    if (tid < ND) {
        int g = tid >> 3, jj = tid & 7;
        bias_s[tid] = bgp[g][j0 + jj];
    }
    // zero the h(0) region this CTA owns
    if (tid < BG*8) {
        int r = tid >> 3, jj = tid & 7;
        g_h[0][(b0 + r)*HID + j0 + jj] = 0.0f;
    }

    // GEMM mapping: 16 warps = 8 K-segments x 2 row-halves
    const int kseg = wid >> 1;               // 0..7
    const int rh   = wid & 1;                // 0..1 -> rows 16*rh..16*rh+15
    const int rg   = lane >> 2;              // 0..7 -> rows 16rh+2rg, +1
    const int cg   = lane & 3;               // cols 8cg..8cg+7
    const int kb   = kseg * 24;
    const int s0   = (2*cg) & 7;
    const int s1   = (2*cg + 1) & 7;
    const float* xr0 = inp_s + (16*rh + 2*rg) * GD;   // x key = rg for both rows
    const float* wc0 = w_s   + (8*cg) * GD;

    // staging mapping: warp w stages rows {2w, 2w+1}; key (row>>1)&7 = w&7
    const int dr    = lane >> 4;              // 0..1
    const int dk    = lane & 15;              // 0..15
    const int srow_ = 2*wid + dr;
    const int ssw   = wid & 7;
    float* sdst = inp_s + srow_ * GD;
    const unsigned int sdst_s = (unsigned int)__cvta_generic_to_shared(sdst);
    const int* idrow = ids + (b0 + srow_)*SEQ;

    // epilogue mapping: threads 0..255 -> one (row, hidden-unit) each
    const int eb  = (tid & 255) >> 3;
    const int ejj = tid & 7;
    const bool epi = (tid < 256);

    float cst  = 0.0f;
    float mmax = -INFINITY;

    // ---- pre-stage embedding for t=0 ----
    {
        int id0 = __ldg(idrow + 0);
        const float4* erow = (const float4*)(emb + (size_t)id0 * EMBED);
        #pragma unroll
        for (int o = 0; o < 4; o++) {
            int k4 = 128 + o*16 + dk;
            *(float4*)(sdst + ((k4 ^ ssw) << 2)) = erow[o*16 + dk];
        }
    }

    unsigned long long hbase = *((volatile unsigned long long*)hctr);

    ticket_barrier();                        // h(0), emb(0), hbase settled

    for (int t = 0; t < SEQ; t++) {
        const float* hcur = g_h[t & 1];

        // ---- stage h_prev via cp.async (.cg = L2-direct) ----
        {
            const float4* hrow = (const float4*)(hcur + (size_t)(b0 + srow_) * HID);
            #pragma unroll
            for (int oct = 0; oct < 8; oct++) {
                int k4 = oct*16 + dk;
                cp16_cg(sdst_s + ((k4 ^ ssw) << 4), hrow + k4);
            }
            CP_COMMIT();
        }
        CP_WAITALL();                        // h(this step) + emb(issued last step)
        __syncthreads();

        // ---- register-tiled split-K GEMM (2 rows x 8 cols per lane) ----
        unsigned long long acc[2][8];
        #pragma unroll
        for (int r = 0; r < 2; r++)
            #pragma unroll
            for (int c = 0; c < 8; c++) acc[r][c] = 0ULL;

        {
            ulonglong2 xa[2], xb[2];
            loadx2(xa, xr0, kb, rg);
            #pragma unroll
            for (int kk = 0; kk < 24; kk += 2) {
                loadx2(xb, xr0, kb + kk + 1, rg);
                gemm_step(acc, xa, wc0, ((kb+kk)   ^ s0) << 2, ((kb+kk)   ^ s1) << 2);
                if (kk + 2 < 24) loadx2(xa, xr0, kb + kk + 2, rg);
                gemm_step(acc, xb, wc0, ((kb+kk+1) ^ s0) << 2, ((kb+kk+1) ^ s1) << 2);
            }
        }

        // ---- one-shot partial store (row-halves write disjoint rows) ----
        {
            float* myset = part_s + kseg*SET_STRIDE;
            #pragma unroll
            for (int c = 0; c < 8; c++)
                #pragma unroll
                for (int r = 0; r < 2; r++)
                    myset[(4*c + cg)*33 + 16*rh + 2*rg + r] = sum2(acc[r][c]);
        }
        __syncthreads();

        // ---- emb prefetch for t+1: cp.async, waited at next step top ----
        if (t + 1 < SEQ) {
            int id1 = __ldg(idrow + t + 1);
            const float4* erow = (const float4*)(emb + (size_t)id1 * EMBED);
            #pragma unroll
            for (int o = 0; o < 4; o++) {
                int k4 = 128 + o*16 + dk;
                cp16_cg(sdst_s + ((k4 ^ ssw) << 4), erow + o*16 + dk);
            }
            CP_COMMIT();
        }

        // ---- epilogue (threads 0..255): sum 8 segments, gates, state ----
        if (epi) {
            float pf = bias_s[ 0 + ejj];
            float pi = bias_s[ 8 + ejj];
            float po = bias_s[16 + ejj];
            float pg = bias_s[24 + ejj];
            #pragma unroll
            for (int s = 0; s < 8; s++) {
                const float* sp = part_s + s*SET_STRIDE + eb;
                pf += sp[(4*ejj + 0)*33];
                pi += sp[(4*ejj + 1)*33];
                po += sp[(4*ejj + 2)*33];
                pg += sp[(4*ejj + 3)*33];
            }
            float f  = sigf(pf);
            float iv = sigf(pi);
            float o  = sigf(po);
            float gg = tanhfast(pg);
            cst = f*cst + iv*gg;
            float h = o * tanhfast(cst);
            mmax = fmaxf(mmax, h);
            g_h[(t + 1) & 1][(size_t)(b0 + eb)*HID + j0 + ejj] = h;
        }

        // ---- 64-CTA half barrier (skip after the last step) ----
        if (t + 1 < SEQ)
            half_barrier(hctr, hbase + (unsigned long long)HALF_CTAS * (t + 1));
    }

    // ---- max-over-time out, then tiny FC on CTA 0 ----
    if (epi)
        g_maxh[(size_t)(b0 + eb)*HID + j0 + ejj] = mmax;
    ticket_barrier();

    if (cta == 0 && tid < 256) {
        int b  = tid >> 2;
        int ci = tid & 3;
        const float4* a4 = (const float4*)(g_maxh + (size_t)b * HID);
        const float4* w4 = (const float4*)(fcw + (size_t)ci * HID);
        float acc = fcb[ci];
        #pragma unroll 4
        for (int k = 0; k < HID/4; k++) {
            float4 a = __ldcg(a4 + k);
            float4 w = w4[k];
            acc += a.x*w.x + a.y*w.y + a.z*w.z + a.w*w.w;
        }
        out[b*NCLS + ci] = acc;
    }
}

extern "C" void kernel_launch(void* const* d_in, const int* in_sizes, int n_in,
                              void* d_out, int out_size)
{
    const int*   ids = (const int*)  d_in[0];
    const float* emb = (const float*)d_in[1];
    const float* Wf  = (const float*)d_in[2];
    const float* bf  = (const float*)d_in[3];
    const float* Wi  = (const float*)d_in[4];
    const float* bi  = (const float*)d_in[5];
    const float* Wo  = (const float*)d_in[6];
    const float* bo  = (const float*)d_in[7];
    const float* Wc  = (const float*)d_in[8];
    const float* bc  = (const float*)d_in[9];
    const float* fcw = (const float*)d_in[10];
    const float* fcb = (const float*)d_in[11];
    float* out = (float*)d_out;

    cudaFuncSetAttribute(lstm_persistent,
                         cudaFuncAttributeMaxDynamicSharedMemorySize, SMEM_BYTES);
    lstm_persistent<<<NBLK, NTHR, SMEM_BYTES>>>(ids, emb, Wf, bf, Wi, bi,
                                                Wo, bo, Wc, bc, fcw, fcb, out);
}

// round 9
// speedup vs baseline: 1.2712x; 1.2712x over previous
#include <cuda_runtime.h>
#include <math.h>

#define BATCH 64
#define SEQ   512
#define EMBED 256
#define HID   512
#define GD    768     // HID + EMBED
#define NCLS  4

#define NBLK  128     // 2 batch halves x 64 column groups
#define NTHR  256     // 8 warps
#define BG    32      // batch rows per CTA
#define ND    32      // dot-columns per CTA = 4 gates * 8 hidden units
#define K4T   192     // GD / 4 (float4 count per row)
#define HALF_CTAS 64

// SMEM: w[32][768] + inp[32][768] (XOR-swizzled) + 8 partial sets + bias
#define SM_W       0
#define SM_INP     (32*768)
#define SM_PART    (SM_INP + 32*768)
#define SET_STRIDE 1056                 // 32 cols' x 33 (row-padded)
#define SM_BIAS    (SM_PART + 8*SET_STRIDE)
#define SMEM_FLOATS (SM_BIAS + 32)
#define SMEM_BYTES  (SMEM_FLOATS * 4)   // 230,528 B

__device__ float g_h[2][BATCH*HID];
__device__ float g_maxh[BATCH*HID];
__device__ unsigned long long g_cnt;          // full-grid ticket counter
__device__ unsigned long long g_half[64];     // per-half counters (slots 0, 32)

__device__ __forceinline__ float sigf(float x)     { return 1.0f / (1.0f + __expf(-x)); }
__device__ __forceinline__ float tanhfast(float x) { return 2.0f / (1.0f + __expf(-2.0f*x)) - 1.0f; }

__device__ __forceinline__ void fma2(unsigned long long &d,
                                     unsigned long long a, unsigned long long b) {
    asm("fma.rn.f32x2 %0, %1, %2, %0;" : "+l"(d) : "l"(a), "l"(b));
}
__device__ __forceinline__ void mul2(unsigned long long &d,
                                     unsigned long long a, unsigned long long b) {
    asm("mul.rn.f32x2 %0, %1, %2;" : "=l"(d) : "l"(a), "l"(b));
}
__device__ __forceinline__ float sum2(unsigned long long v) {
    float lo, hi;
    asm("mov.b64 {%0,%1}, %2;" : "=f"(lo), "=f"(hi) : "l"(v));
    return lo + hi;
}

// cp.async 16B, L2-only (.cg): required for h (cross-SM coherence), fine for emb
__device__ __forceinline__ void cp16_cg(unsigned int saddr, const void* g) {
    asm volatile("cp.async.cg.shared.global [%0], [%1], 16;" :: "r"(saddr), "l"(g));
}
#define CP_COMMIT()  asm volatile("cp.async.commit_group;" ::: "memory")
#define CP_WAITALL() asm volatile("cp.async.wait_all;"     ::: "memory")

// Full-grid ticket barrier (fence-free; init and finish only).
__device__ __forceinline__ void ticket_barrier() {
    __syncthreads();
    if (threadIdx.x == 0) {
        unsigned long long ticket;
        asm volatile("atom.release.gpu.add.u64 %0, [%1], %2;"
                     : "=l"(ticket) : "l"(&g_cnt), "l"(1ULL) : "memory");
        unsigned long long target = (ticket / NBLK + 1ULL) * (unsigned long long)NBLK;
        unsigned long long cur;
        do {
            asm volatile("ld.acquire.gpu.u64 %0, [%1];"
                         : "=l"(cur) : "l"(&g_cnt) : "memory");
        } while (cur < target);
    }
    __syncthreads();
}

// Per-half barrier: no-return release reduction + acquire poll vs per-replay base.
__device__ __forceinline__ void half_barrier(unsigned long long* ctr,
                                             unsigned long long target) {
    __syncthreads();
    if (threadIdx.x == 0) {
        asm volatile("red.release.gpu.add.u64 [%0], %1;"
                     :: "l"(ctr), "l"(1ULL) : "memory");
        unsigned long long cur;
        do {
            asm volatile("ld.acquire.gpu.u64 %0, [%1];"
                         : "=l"(cur) : "l"(ctr) : "memory");
        } while (cur < target);
    }
    __syncthreads();
}

extern "C" __global__ void __launch_bounds__(NTHR, 1)
lstm_persistent(const int*   __restrict__ ids,
                const float* __restrict__ emb,
                const float* __restrict__ Wf, const float* __restrict__ bf,
                const float* __restrict__ Wi, const float* __restrict__ bi,
                const float* __restrict__ Wo, const float* __restrict__ bo,
                const float* __restrict__ Wc, const float* __restrict__ bc,
                const float* __restrict__ fcw, const float* __restrict__ fcb,
                float* __restrict__ out)
{
    extern __shared__ float sm[];
    float* w_s    = sm + SM_W;
    float* inp_s  = sm + SM_INP;
    float* part_s = sm + SM_PART;
    float* bias_s = sm + SM_BIAS;

    const int tid  = threadIdx.x;
    const int cta  = blockIdx.x;
    const int half = cta & 1;
    const int b0   = half * BG;             // batch half
    const int j0   = (cta >> 1) * 8;        // hidden-unit group (8 units)
    const int wid  = tid >> 5;              // 0..7
    const int lane = tid & 31;

    unsigned long long* hctr = &g_half[half * 32];

    const float* Wg[4]  = {Wf, Wi, Wo, Wc};
    const float* bgp[4] = {bf, bi, bo, bc};

    // ---- one-time: weight slice into swizzled SMEM (key (col>>2)&7) ----
    for (int idx = tid; idx < ND*K4T; idx += NTHR) {
        int d  = idx / K4T;
        int k4 = idx - d*K4T;
        int g  = d >> 3, jj = d & 7;
        float4 v = ((const float4*)(Wg[g] + (size_t)(j0 + jj) * GD))[k4];
        *(float4*)(w_s + d*GD + ((k4 ^ ((d >> 2) & 7)) << 2)) = v;
    }
    if (tid < ND) {
        int g = tid >> 3, jj = tid & 7;
        bias_s[tid] = bgp[g][j0 + jj];
    }
    // zero the h(0) region this CTA owns
    if (tid < BG*8) {
        int r = tid >> 3, jj = tid & 7;
        g_h[0][(b0 + r)*HID + j0 + jj] = 0.0f;
    }

    // GEMM mapping: 8 warps, lane tile 8 rows x 8 cols, 16-way K split
    // (lanes 0-15 = segment 2*wid, lanes 16-31 = segment 2*wid+1)
    const int lh = lane >> 4;                // 0..1 intra-warp K half
    const int li = lane & 15;
    const int rg = li >> 2;                  // 0..3 -> rows 8rg..8rg+7
    const int cg = li & 3;                   // 0..3 -> cols 8cg..8cg+7
    const int kb = (wid*2 + lh) * 12;        // 16 segments x 12 k4
    const int xk0 = 2*rg;                    // x key, rows 8rg..8rg+3
    const int xk1 = 2*rg + 1;                // x key, rows 8rg+4..8rg+7
    const int wk0 = 2*cg;                    // w key, cols 8cg..8cg+3
    const int wk1 = 2*cg + 1;                // w key, cols 8cg+4..8cg+7
    const float* xr0 = inp_s + (8*rg) * GD;
    const float* wc0 = w_s   + (8*cg) * GD;

    // staging mapping (as R6): warp owns 4 rows stride 4
    const int dr    = lane >> 3;             // 0..3
    const int dk    = lane & 7;              // 0..7
    const int rbase = (wid & 3) + (wid >> 2) * 16;
    const int srow_ = rbase + 4*dr;
    const int ssw   = srow_ >> 2;
    float* sdst = inp_s + srow_ * GD;
    const unsigned int sdst_s = (unsigned int)__cvta_generic_to_shared(sdst);
    const int* idrow = ids + (b0 + srow_)*SEQ;

    // epilogue mapping: one thread per (batch row, hidden unit)
    const int eb  = tid >> 3;                // 0..31
    const int ejj = tid & 7;                 // 0..7

    float cst  = 0.0f;
    float mmax = -INFINITY;

    // ---- pre-stage embedding for t=0 ----
    {
        int id0 = __ldg(idrow + 0);
        const float4* erow = (const float4*)(emb + (size_t)id0 * EMBED);
        #pragma unroll
        for (int o = 0; o < 8; o++) {
            int k4 = (16 + o)*8 + dk;
            *(float4*)(sdst + ((k4 ^ ssw) << 2)) = erow[o*8 + dk];
        }
    }

    unsigned long long hbase = *((volatile unsigned long long*)hctr);

    ticket_barrier();                         // h(0), emb(0), hbase settled

    for (int t = 0; t < SEQ; t++) {
        const float* hcur = g_h[t & 1];

        // ---- stage h_prev via cp.async (.cg = L2-direct) ----
        {
            const float4* hrow = (const float4*)(hcur + (size_t)(b0 + srow_) * HID);
            #pragma unroll
            for (int oct = 0; oct < 16; oct++) {
                int k4 = oct*8 + dk;
                cp16_cg(sdst_s + ((k4 ^ ssw) << 4), hrow + k4);
            }
            CP_COMMIT();
        }
        CP_WAITALL();                         // h(this step) + emb(last step)
        __syncthreads();

        // ---- register-tiled GEMM: 8x8 lane tile, 12 k4 per lane ----
        unsigned long long acc[8][8];
        {
            // kk = 0: init accumulators with mul (no zero-init MOVs)
            int k4 = kb;
            int ox0 = ((k4 ^ xk0) << 2), ox1 = ((k4 ^ xk1) << 2);
            int ow0 = ((k4 ^ wk0) << 2), ow1 = ((k4 ^ wk1) << 2);
            ulonglong2 xv[8];
            #pragma unroll
            for (int r = 0; r < 4; r++) {
                xv[r]   = *(const ulonglong2*)(xr0 + r*GD     + ox0);
                xv[r+4] = *(const ulonglong2*)(xr0 + (r+4)*GD + ox1);
            }
            #pragma unroll
            for (int c = 0; c < 8; c++) {
                ulonglong2 wv = *(const ulonglong2*)(wc0 + c*GD + (c < 4 ? ow0 : ow1));
                #pragma unroll
                for (int r = 0; r < 8; r++) {
                    mul2(acc[r][c], xv[r].x, wv.x);
                    fma2(acc[r][c], xv[r].y, wv.y);
                }
            }
        }
        #pragma unroll
        for (int kk = 1; kk < 12; kk++) {
            int k4 = kb + kk;
            int ox0 = ((k4 ^ xk0) << 2), ox1 = ((k4 ^ xk1) << 2);
            int ow0 = ((k4 ^ wk0) << 2), ow1 = ((k4 ^ wk1) << 2);
            ulonglong2 xv[8];
            #pragma unroll
            for (int r = 0; r < 4; r++) {
                xv[r]   = *(const ulonglong2*)(xr0 + r*GD     + ox0);
                xv[r+4] = *(const ulonglong2*)(xr0 + (r+4)*GD + ox1);
            }
            #pragma unroll
            for (int c = 0; c < 8; c++) {
                ulonglong2 wv = *(const ulonglong2*)(wc0 + c*GD + (c < 4 ? ow0 : ow1));
                #pragma unroll
                for (int r = 0; r < 8; r++) {
                    fma2(acc[r][c], xv[r].x, wv.x);
                    fma2(acc[r][c], xv[r].y, wv.y);
                }
            }
        }

        // ---- fold intra-warp K halves (shfl) + scalar store of 8 partial sets
        //      (scalar: 33-stride layout is NOT float4-aligned for cg!=0) ----
        {
            float* myset = part_s + wid*SET_STRIDE;
            #pragma unroll
            for (int c = 0; c < 8; c++) {
                float v[8];
                #pragma unroll
                for (int r = 0; r < 8; r++) {
                    v[r] = sum2(acc[r][c]);
                    v[r] += __shfl_down_sync(0xffffffffu, v[r], 16);
                }
                if (lh == 0) {
                    float* p = myset + (4*c + cg)*33 + 8*rg;
                    #pragma unroll
                    for (int r = 0; r < 8; r++) p[r] = v[r];
                }
            }
        }
        __syncthreads();

        // ---- emb prefetch for t+1: cp.async, waited at next step top ----
        if (t + 1 < SEQ) {
            int id1 = __ldg(idrow + t + 1);
            const float4* erow = (const float4*)(emb + (size_t)id1 * EMBED);
            #pragma unroll
            for (int o = 0; o < 8; o++) {
                int k4 = (16 + o)*8 + dk;
                cp16_cg(sdst_s + ((k4 ^ ssw) << 4), erow + o*8 + dk);
            }
            CP_COMMIT();
        }

        // ---- epilogue: sum 8 segments, gates, state update ----
        {
            float pf = bias_s[ 0 + ejj];
            float pi = bias_s[ 8 + ejj];
            float po = bias_s[16 + ejj];
            float pg = bias_s[24 + ejj];
            #pragma unroll
            for (int s = 0; s < 8; s++) {
                const float* sp = part_s + s*SET_STRIDE + eb;
                pf += sp[(4*ejj + 0)*33];
                pi += sp[(4*ejj + 1)*33];
                po += sp[(4*ejj + 2)*33];
                pg += sp[(4*ejj + 3)*33];
            }
            float f  = sigf(pf);
            float iv = sigf(pi);
            float o  = sigf(po);
            float gg = tanhfast(pg);
            cst = f*cst + iv*gg;
            float h = o * tanhfast(cst);
            mmax = fmaxf(mmax, h);
            g_h[(t + 1) & 1][(size_t)(b0 + eb)*HID + j0 + ejj] = h;
        }

        // ---- 64-CTA half barrier (skip after the last step) ----
        if (t + 1 < SEQ)
            half_barrier(hctr, hbase + (unsigned long long)HALF_CTAS * (t + 1));
    }

    // ---- max-over-time out, then tiny FC on CTA 0 ----
    g_maxh[(size_t)(b0 + eb)*HID + j0 + ejj] = mmax;
    ticket_barrier();

    if (cta == 0) {
        int b  = tid >> 2;
        int ci = tid & 3;
        const float4* a4 = (const float4*)(g_maxh + (size_t)b * HID);
        const float4* w4 = (const float4*)(fcw + (size_t)ci * HID);
        float acc = fcb[ci];
        #pragma unroll 4
        for (int k = 0; k < HID/4; k++) {
            float4 a = __ldcg(a4 + k);
            float4 w = w4[k];
            acc += a.x*w.x + a.y*w.y + a.z*w.z + a.w*w.w;
        }
        out[b*NCLS + ci] = acc;
    }
}

extern "C" void kernel_launch(void* const* d_in, const int* in_sizes, int n_in,
                              void* d_out, int out_size)
{
    const int*   ids = (const int*)  d_in[0];
    const float* emb = (const float*)d_in[1];
    const float* Wf  = (const float*)d_in[2];
    const float* bf  = (const float*)d_in[3];
    const float* Wi  = (const float*)d_in[4];
    const float* bi  = (const float*)d_in[5];
    const float* Wo  = (const float*)d_in[6];
    const float* bo  = (const float*)d_in[7];
    const float* Wc  = (const float*)d_in[8];
    const float* bc  = (const float*)d_in[9];
    const float* fcw = (const float*)d_in[10];
    const float* fcb = (const float*)d_in[11];
    float* out = (float*)d_out;

    cudaFuncSetAttribute(lstm_persistent,
                         cudaFuncAttributeMaxDynamicSharedMemorySize, SMEM_BYTES);
    lstm_persistent<<<NBLK, NTHR, SMEM_BYTES>>>(ids, emb, Wf, bf, Wi, bi,
                                                Wo, bo, Wc, bc, fcw, fcb, out);
}

// round 10
// speedup vs baseline: 1.3339x; 1.0493x over previous
#include <cuda_runtime.h>
#include <math.h>

#define BATCH 64
#define SEQ   512
#define EMBED 256
#define HID   512
#define GD    768     // HID + EMBED
#define NCLS  4

#define NBLK  128     // 2 batch halves x 64 column groups
#define NTHR  256     // 8 warps
#define BG    32      // batch rows per CTA
#define ND    32      // dot-columns per CTA = 4 gates * 8 hidden units
#define K4T   192     // GD / 4 (float4 count per row)
#define HALF_CTAS 64

// SMEM: w[32][768] + inp[32][768] (XOR-swizzled) + 8 partial sets + bias
#define SM_W       0
#define SM_INP     (32*768)
#define SM_PART    (SM_INP + 32*768)
#define SET_STRIDE 1056                 // 32 cols' x 33 (row-padded)
#define SM_BIAS    (SM_PART + 8*SET_STRIDE)
#define SMEM_FLOATS (SM_BIAS + 32)
#define SMEM_BYTES  (SMEM_FLOATS * 4)   // 230,528 B

__device__ float g_h[2][BATCH*HID];
__device__ float g_maxh[BATCH*HID];
__device__ unsigned long long g_cnt;          // full-grid ticket counter
__device__ unsigned long long g_half[64];     // per-half counters (slots 0, 32)

__device__ __forceinline__ float sigf(float x)     { return 1.0f / (1.0f + __expf(-x)); }
__device__ __forceinline__ float tanhfast(float x) { return 2.0f / (1.0f + __expf(-2.0f*x)) - 1.0f; }

__device__ __forceinline__ void fma2(unsigned long long &d,
                                     unsigned long long a, unsigned long long b) {
    asm("fma.rn.f32x2 %0, %1, %2, %0;" : "+l"(d) : "l"(a), "l"(b));
}
__device__ __forceinline__ void mul2(unsigned long long &d,
                                     unsigned long long a, unsigned long long b) {
    asm("mul.rn.f32x2 %0, %1, %2;" : "=l"(d) : "l"(a), "l"(b));
}
__device__ __forceinline__ float sum2(unsigned long long v) {
    float lo, hi;
    asm("mov.b64 {%0,%1}, %2;" : "=f"(lo), "=f"(hi) : "l"(v));
    return lo + hi;
}

// cp.async 16B, L2-only (.cg): required for h (cross-SM coherence), fine for emb
__device__ __forceinline__ void cp16_cg(unsigned int saddr, const void* g) {
    asm volatile("cp.async.cg.shared.global [%0], [%1], 16;" :: "r"(saddr), "l"(g));
}
#define CP_COMMIT()  asm volatile("cp.async.commit_group;" ::: "memory")
#define CP_WAITALL() asm volatile("cp.async.wait_all;"     ::: "memory")

// Full-grid ticket barrier (fence-free; init and finish only).
__device__ __forceinline__ void ticket_barrier() {
    __syncthreads();
    if (threadIdx.x == 0) {
        unsigned long long ticket;
        asm volatile("atom.release.gpu.add.u64 %0, [%1], %2;"
                     : "=l"(ticket) : "l"(&g_cnt), "l"(1ULL) : "memory");
        unsigned long long target = (ticket / NBLK + 1ULL) * (unsigned long long)NBLK;
        unsigned long long cur;
        do {
            asm volatile("ld.acquire.gpu.u64 %0, [%1];"
                         : "=l"(cur) : "l"(&g_cnt) : "memory");
        } while (cur < target);
    }
    __syncthreads();
}

__device__ __forceinline__ void loadx(ulonglong2 xv[4], const float* xr0, int k4, int rg) {
    int ox = ((k4 ^ rg) << 2);
    #pragma unroll
    for (int r = 0; r < 4; r++)
        xv[r] = *(const ulonglong2*)(xr0 + r*GD + ox);
}

__device__ __forceinline__ void gemm_step(unsigned long long acc[4][8],
                                          const ulonglong2 xv[4],
                                          const float* wc0, int o0, int o1) {
    #pragma unroll
    for (int c = 0; c < 8; c++) {
        ulonglong2 wv = *(const ulonglong2*)(wc0 + c*GD + (c < 4 ? o0 : o1));
        #pragma unroll
        for (int r = 0; r < 4; r++) {
            fma2(acc[r][c], xv[r].x, wv.x);
            fma2(acc[r][c], xv[r].y, wv.y);
        }
    }
}

// emb-part GEMM (8 k4, K 512..767): re-initializes acc via mul2 on first k4.
__device__ __forceinline__ void emb_gemm(unsigned long long acc[4][8],
                                         const float* xr0, const float* wc0,
                                         int kbe, int rg, int s0, int s1) {
    {
        int k4 = kbe;
        int ox = ((k4 ^ rg) << 2), o0 = ((k4 ^ s0) << 2), o1 = ((k4 ^ s1) << 2);
        ulonglong2 xv[4];
        #pragma unroll
        for (int r = 0; r < 4; r++)
            xv[r] = *(const ulonglong2*)(xr0 + r*GD + ox);
        #pragma unroll
        for (int c = 0; c < 8; c++) {
            ulonglong2 wv = *(const ulonglong2*)(wc0 + c*GD + (c < 4 ? o0 : o1));
            #pragma unroll
            for (int r = 0; r < 4; r++) {
                mul2(acc[r][c], xv[r].x, wv.x);
                fma2(acc[r][c], xv[r].y, wv.y);
            }
        }
    }
    #pragma unroll
    for (int kk = 1; kk < 8; kk++) {
        int k4 = kbe + kk;
        ulonglong2 xv[4];
        loadx(xv, xr0, k4, rg);
        gemm_step(acc, xv, wc0, ((k4 ^ s0) << 2), ((k4 ^ s1) << 2));
    }
}

extern "C" __global__ void __launch_bounds__(NTHR, 1)
lstm_persistent(const int*   __restrict__ ids,
                const float* __restrict__ emb,
                const float* __restrict__ Wf, const float* __restrict__ bf,
                const float* __restrict__ Wi, const float* __restrict__ bi,
                const float* __restrict__ Wo, const float* __restrict__ bo,
                const float* __restrict__ Wc, const float* __restrict__ bc,
                const float* __restrict__ fcw, const float* __restrict__ fcb,
                float* __restrict__ out)
{
    extern __shared__ float sm[];
    float* w_s    = sm + SM_W;
    float* inp_s  = sm + SM_INP;
    float* part_s = sm + SM_PART;
    float* bias_s = sm + SM_BIAS;

    const int tid  = threadIdx.x;
    const int cta  = blockIdx.x;
    const int half = cta & 1;
    const int b0   = half * BG;             // batch half
    const int j0   = (cta >> 1) * 8;        // hidden-unit group (8 units)
    const int wid  = tid >> 5;              // 0..7
    const int lane = tid & 31;

    unsigned long long* hctr = &g_half[half * 32];

    const float* Wg[4]  = {Wf, Wi, Wo, Wc};
    const float* bgp[4] = {bf, bi, bo, bc};

    // ---- one-time: weight slice into swizzled SMEM (key (col>>2)&7) ----
    for (int idx = tid; idx < ND*K4T; idx += NTHR) {
        int d  = idx / K4T;
        int k4 = idx - d*K4T;
        int g  = d >> 3, jj = d & 7;
        float4 v = ((const float4*)(Wg[g] + (size_t)(j0 + jj) * GD))[k4];
        *(float4*)(w_s + d*GD + ((k4 ^ ((d >> 2) & 7)) << 2)) = v;
    }
    if (tid < ND) {
        int g = tid >> 3, jj = tid & 7;
        bias_s[tid] = bgp[g][j0 + jj];
    }
    // zero the h(0) region this CTA owns
    if (tid < BG*8) {
        int r = tid >> 3, jj = tid & 7;
        g_h[0][(b0 + r)*HID + j0 + jj] = 0.0f;
    }

    // GEMM mapping: 8 warps, lane tile 4 rows x 8 cols
    // h-part:   per-warp K segment kbh = wid*16      (16 k4, K 0..511)
    // emb-part: per-warp K segment kbe = 128 + wid*8 ( 8 k4, K 512..767)
    const int rg  = lane >> 2;               // rows 4rg..4rg+3 (x key = rg)
    const int cg  = lane & 3;                // cols 8cg..8cg+7
    const int kbh = wid * 16;
    const int kbe = 128 + wid * 8;
    const int s0  = (2*cg) & 7;              // w key, cols 8cg..8cg+3
    const int s1  = (2*cg + 1) & 7;          // w key, cols 8cg+4..8cg+7
    const float* xr0 = inp_s + (4*rg) * GD;
    const float* wc0 = w_s   + (8*cg) * GD;

    // staging mapping: warp owns 4 rows stride 4
    const int dr    = lane >> 3;              // 0..3
    const int dk    = lane & 7;               // 0..7
    const int rbase = (wid & 3) + (wid >> 2) * 16;
    const int srow_ = rbase + 4*dr;
    const int ssw   = srow_ >> 2;
    float* sdst = inp_s + srow_ * GD;
    const unsigned int sdst_s = (unsigned int)__cvta_generic_to_shared(sdst);
    const int* idrow = ids + (b0 + srow_)*SEQ;

    // epilogue mapping: one thread per (batch row, hidden unit)
    const int eb  = tid >> 3;                 // 0..31
    const int ejj = tid & 7;                  // 0..7

    float cst  = 0.0f;
    float mmax = -INFINITY;

    // ---- pre-stage embedding for t=0 ----
    {
        int id0 = __ldg(idrow + 0);
        const float4* erow = (const float4*)(emb + (size_t)id0 * EMBED);
        #pragma unroll
        for (int o = 0; o < 8; o++) {
            int k4 = (16 + o)*8 + dk;
            *(float4*)(sdst + ((k4 ^ ssw) << 2)) = erow[o*8 + dk];
        }
    }

    unsigned long long hbase = *((volatile unsigned long long*)hctr);

    ticket_barrier();                          // h(0), emb(0), hbase settled

    // acc carries the emb contribution for the *current* step across iterations
    unsigned long long acc[4][8];
    emb_gemm(acc, xr0, wc0, kbe, rg, s0, s1);  // emb contribution for t=0

    for (int t = 0; t < SEQ; t++) {
        // ---- 1. stage h(t) via cp.async (.cg = L2-direct) ----
        {
            const float4* hrow = (const float4*)(g_h[t & 1] + (size_t)(b0 + srow_) * HID);
            #pragma unroll
            for (int oct = 0; oct < 16; oct++) {
                int k4 = oct*8 + dk;
                cp16_cg(sdst_s + ((k4 ^ ssw) << 4), hrow + k4);
            }
            CP_COMMIT();
        }
        CP_WAITALL();
        __syncthreads();

        // ---- 2. h-part GEMM: accumulate onto emb contribution ----
        {
            ulonglong2 xa[4], xb[4];
            loadx(xa, xr0, kbh, rg);
            #pragma unroll
            for (int kk = 0; kk < 16; kk += 2) {
                loadx(xb, xr0, kbh + kk + 1, rg);
                gemm_step(acc, xa, wc0, ((kbh+kk)   ^ s0) << 2, ((kbh+kk)   ^ s1) << 2);
                if (kk + 2 < 16) loadx(xa, xr0, kbh + kk + 2, rg);
                gemm_step(acc, xb, wc0, ((kbh+kk+1) ^ s0) << 2, ((kbh+kk+1) ^ s1) << 2);
            }
        }

        // ---- 3. fold to 8 partial sets (scalar, conflict-free) ----
        {
            float* myset = part_s + wid*SET_STRIDE;
            #pragma unroll
            for (int c = 0; c < 8; c++)
                #pragma unroll
                for (int r = 0; r < 4; r++)
                    myset[(4*c + cg)*33 + 4*rg + r] = sum2(acc[r][c]);
        }
        __syncthreads();

        const bool more = (t + 1 < SEQ);

        // ---- 4. emb(t+1) prefetch: cp.async issued early ----
        if (more) {
            int id1 = __ldg(idrow + t + 1);
            const float4* erow = (const float4*)(emb + (size_t)id1 * EMBED);
            #pragma unroll
            for (int o = 0; o < 8; o++) {
                int k4 = (16 + o)*8 + dk;
                cp16_cg(sdst_s + ((k4 ^ ssw) << 4), erow + o*8 + dk);
            }
            CP_COMMIT();
        }

        // ---- 5. epilogue: sum 8 segments, gates, state update, h store ----
        {
            float pf = bias_s[ 0 + ejj];
            float pi = bias_s[ 8 + ejj];
            float po = bias_s[16 + ejj];
            float pg = bias_s[24 + ejj];
            #pragma unroll
            for (int s = 0; s < 8; s++) {
                const float* sp = part_s + s*SET_STRIDE + eb;
                pf += sp[(4*ejj + 0)*33];
                pi += sp[(4*ejj + 1)*33];
                po += sp[(4*ejj + 2)*33];
                pg += sp[(4*ejj + 3)*33];
            }
            float f  = sigf(pf);
            float iv = sigf(pi);
            float o  = sigf(po);
            float gg = tanhfast(pg);
            cst = f*cst + iv*gg;
            float h = o * tanhfast(cst);
            mmax = fmaxf(mmax, h);
            g_h[(t + 1) & 1][(size_t)(b0 + eb)*HID + j0 + ejj] = h;
        }

        // ---- 6. arrive at half-barrier, hide emb-GEMM(t+1) in the wait ----
        if (more) {
            __syncthreads();                   // all h stores issued
            if (tid == 0)
                asm volatile("red.release.gpu.add.u64 [%0], %1;"
                             :: "l"(hctr), "l"(1ULL) : "memory");

            CP_WAITALL();                      // emb(t+1) landed (this thread)
            __syncthreads();                   // visible CTA-wide

            emb_gemm(acc, xr0, wc0, kbe, rg, s0, s1);   // emb contrib for t+1

            if (tid == 0) {
                unsigned long long target =
                    hbase + (unsigned long long)HALF_CTAS * (t + 1);
                unsigned long long cur;
                do {
                    asm volatile("ld.acquire.gpu.u64 %0, [%1];"
                                 : "=l"(cur) : "l"(hctr) : "memory");
                } while (cur < target);
            }
            __syncthreads();                   // barrier complete
        }
    }

    // ---- max-over-time out, then tiny FC on CTA 0 ----
    g_maxh[(size_t)(b0 + eb)*HID + j0 + ejj] = mmax;
    ticket_barrier();

    if (cta == 0) {
        int b  = tid >> 2;
        int ci = tid & 3;
        const float4* a4 = (const float4*)(g_maxh + (size_t)b * HID);
        const float4* w4 = (const float4*)(fcw + (size_t)ci * HID);
        float acc0 = fcb[ci];
        #pragma unroll 4
        for (int k = 0; k < HID/4; k++) {
            float4 a = __ldcg(a4 + k);
            float4 w = w4[k];
            acc0 += a.x*w.x + a.y*w.y + a.z*w.z + a.w*w.w;
        }
        out[b*NCLS + ci] = acc0;
    }
}

extern "C" void kernel_launch(void* const* d_in, const int* in_sizes, int n_in,
                              void* d_out, int out_size)
{
    const int*   ids = (const int*)  d_in[0];
    const float* emb = (const float*)d_in[1];
    const float* Wf  = (const float*)d_in[2];
    const float* bf  = (const float*)d_in[3];
    const float* Wi  = (const float*)d_in[4];
    const float* bi  = (const float*)d_in[5];
    const float* Wo  = (const float*)d_in[6];
    const float* bo  = (const float*)d_in[7];
    const float* Wc  = (const float*)d_in[8];
    const float* bc  = (const float*)d_in[9];
    const float* fcw = (const float*)d_in[10];
    const float* fcb = (const float*)d_in[11];
    float* out = (float*)d_out;

    cudaFuncSetAttribute(lstm_persistent,
                         cudaFuncAttributeMaxDynamicSharedMemorySize, SMEM_BYTES);
    lstm_persistent<<<NBLK, NTHR, SMEM_BYTES>>>(ids, emb, Wf, bf, Wi, bi,
                                                Wo, bo, Wc, bc, fcw, fcb, out);
}